// round 1
// baseline (speedup 1.0000x reference)
#include <cuda_runtime.h>

// RNN: B=8192, T=2048, I=2, H=20.
//  h_{t+1} = tanh(x_t @ W_ih^T + b_ih + b_hh + h_t @ W_hh^T)
//  out = h_T @ fc_w^T + fc_b ; h_state = h_T
//
// Strategy: 2 batches packed per thread via fma.rn.f32x2 (FFMA2); 10 threads
// per batch-pair, each owning 2 hidden rows (weights in registers, pre-scaled
// by 2*log2(e) so tanh = 1 - 2*rcp(ex2(A)+1) with no extra multiply).
// h state in double-buffered SMEM, one __syncthreads per timestep.

#define Bq 8192
#define Tq 2048
#define Hq 20
#define NPAIR (Bq / 2)           // 4096
#define PPC 28                   // pairs per CTA
#define TPB (PPC * 10)           // 280 threads
#define NCTA ((NPAIR + PPC - 1) / PPC)  // 147

typedef unsigned long long u64;

__device__ __forceinline__ u64 pack2(float lo, float hi) {
    u64 r;
    asm("mov.b64 %0, {%1, %2};" : "=l"(r) : "f"(lo), "f"(hi));
    return r;
}
__device__ __forceinline__ void unpack2(u64 v, float& lo, float& hi) {
    asm("mov.b64 {%0, %1}, %2;" : "=f"(lo), "=f"(hi) : "l"(v));
}
__device__ __forceinline__ u64 fma2(u64 a, u64 b, u64 c) {
    u64 d;
    asm("fma.rn.f32x2 %0, %1, %2, %3;" : "=l"(d) : "l"(a), "l"(b), "l"(c));
    return d;
}
// Input A is already 2*log2(e)*a ; tanh(a) = 1 - 2/(2^A + 1)
__device__ __forceinline__ float tanh_scaled(float A) {
    float e;
    asm("ex2.approx.f32 %0, %1;" : "=f"(e) : "f"(A));
    float r;
    asm("rcp.approx.f32 %0, %1;" : "=f"(r) : "f"(e + 1.0f));
    return fmaf(-2.0f, r, 1.0f);
}

__global__ void __launch_bounds__(TPB, 1)
rnn_kernel(const float* __restrict__ x,
           const float* __restrict__ Wih,
           const float* __restrict__ Whh,
           const float* __restrict__ bih,
           const float* __restrict__ bhh,
           const float* __restrict__ fcw,
           const float* __restrict__ fcb,
           float* __restrict__ out,   // [B]
           float* __restrict__ hs)    // [B, H]
{
    const float SC = 2.8853900817779268f;  // 2 * log2(e)

    const int lp  = threadIdx.x / 10;      // local pair 0..27
    const int sub = threadIdx.x % 10;      // sub-thread within pair
    const int p   = blockIdx.x * PPC + lp; // global pair
    const bool active = (p < NPAIR);
    const int pc  = active ? p : 0;        // clamped for safe loads
    const int b0  = 2 * pc;
    const int b1  = 2 * pc + 1;
    const int j0  = 2 * sub;               // this thread's hidden rows
    const int j1  = j0 + 1;

    // ---- Per-thread constants (scaled by SC, splatted to f32x2) ----
    u64 wA[Hq], wB[Hq];
#pragma unroll
    for (int k = 0; k < Hq; k++) {
        float a = Whh[j0 * Hq + k] * SC;
        float b = Whh[j1 * Hq + k] * SC;
        wA[k] = pack2(a, a);
        wB[k] = pack2(b, b);
    }
    float wi00 = Wih[j0 * 2 + 0] * SC, wi01 = Wih[j0 * 2 + 1] * SC;
    float wi10 = Wih[j1 * 2 + 0] * SC, wi11 = Wih[j1 * 2 + 1] * SC;
    u64 wv00 = pack2(wi00, wi00), wv01 = pack2(wi01, wi01);
    u64 wv10 = pack2(wi10, wi10), wv11 = pack2(wi11, wi11);
    float bs0 = (bih[j0] + bhh[j0]) * SC;
    float bs1 = (bih[j1] + bhh[j1]) * SC;
    u64 bv0 = pack2(bs0, bs0), bv1 = pack2(bs1, bs1);

    // ---- Double-buffered hidden state in SMEM ----
    __shared__ u64 hbuf[2][PPC][Hq];
    for (int i = threadIdx.x; i < PPC * Hq; i += TPB)
        (&hbuf[0][0][0])[i] = 0ull;
    __syncthreads();

    const float2* xp0 = (const float2*)(x + (size_t)b0 * Tq * 2);
    const float2* xp1 = (const float2*)(x + (size_t)b1 * Tq * 2);

    u64 r0 = 0, r1 = 0;  // this thread's latest h rows (packed)

    const u64* rdA = &hbuf[0][lp][0];
    u64*       wrA = &hbuf[1][lp][0];
    const u64* rdB = &hbuf[1][lp][0];
    u64*       wrB = &hbuf[0][lp][0];

    auto step = [&](const u64* __restrict__ rd, u64* __restrict__ wr,
                    float2 xa, float2 xb) {
        u64 xv0 = pack2(xa.x, xb.x);
        u64 xv1 = pack2(xa.y, xb.y);
        u64 acc0 = fma2(xv1, wv01, bv0); acc0 = fma2(xv0, wv00, acc0);
        u64 acc1 = fma2(xv1, wv11, bv1); acc1 = fma2(xv0, wv10, acc1);
        u64 hv[Hq];
#pragma unroll
        for (int k = 0; k < Hq; k++) hv[k] = rd[k];
#pragma unroll
        for (int k = 0; k < Hq; k++) {
            acc0 = fma2(hv[k], wA[k], acc0);
            acc1 = fma2(hv[k], wB[k], acc1);
        }
        float a0, a1, c0, c1;
        unpack2(acc0, a0, a1);
        unpack2(acc1, c0, c1);
        r0 = pack2(tanh_scaled(a0), tanh_scaled(a1));
        r1 = pack2(tanh_scaled(c0), tanh_scaled(c1));
        wr[j0] = r0;
        wr[j1] = r1;
        __syncthreads();
    };

    // Software pipeline: x kept 2 steps ahead in registers.
    float2 xa0 = xp0[0], xb0 = xp1[0];   // t even
    float2 xa1 = xp0[1], xb1 = xp1[1];   // t odd

    for (int t = 0; t < Tq; t += 2) {
        int tn = (t + 2 < Tq) ? t + 2 : Tq - 1;
        float2 na = xp0[tn], nb = xp1[tn];
        step(rdA, wrA, xa0, xb0);        // time t   : read buf0, write buf1
        xa0 = na; xb0 = nb;

        int tn2 = (t + 3 < Tq) ? t + 3 : Tq - 1;
        float2 na2 = xp0[tn2], nb2 = xp1[tn2];
        step(rdB, wrB, xa1, xb1);        // time t+1 : read buf1, write buf0
        xa1 = na2; xb1 = nb2;
    }
    // T even -> final h_T resides in hbuf[0]; r0/r1 hold this thread's rows.

    if (active) {
        float v0, v1;
        unpack2(r0, v0, v1);
        hs[(size_t)b0 * Hq + j0] = v0;
        hs[(size_t)b1 * Hq + j0] = v1;
        unpack2(r1, v0, v1);
        hs[(size_t)b0 * Hq + j1] = v0;
        hs[(size_t)b1 * Hq + j1] = v1;

        if (sub == 0) {
            const u64* hr = &hbuf[0][lp][0];
            float s0 = fcb[0], s1 = fcb[0];
#pragma unroll
            for (int k = 0; k < Hq; k++) {
                float lo, hi;
                unpack2(hr[k], lo, hi);
                float w = fcw[k];
                s0 = fmaf(w, lo, s0);
                s1 = fmaf(w, hi, s1);
            }
            out[b0] = s0;
            out[b1] = s1;
        }
    }
}

extern "C" void kernel_launch(void* const* d_in, const int* in_sizes, int n_in,
                              void* d_out, int out_size) {
    const float* x   = (const float*)d_in[0];
    const float* Wih = (const float*)d_in[1];
    const float* Whh = (const float*)d_in[2];
    const float* bih = (const float*)d_in[3];
    const float* bhh = (const float*)d_in[4];
    const float* fcw = (const float*)d_in[5];
    const float* fcb = (const float*)d_in[6];
    float* out = (float*)d_out;            // first B floats: fc output
    float* hs  = out + Bq;                 // next B*H floats: h_state
    rnn_kernel<<<NCTA, TPB>>>(x, Wih, Whh, bih, bhh, fcw, fcb, out, hs);
}

// round 2
// speedup vs baseline: 1.7148x; 1.7148x over previous
#include <cuda_runtime.h>

// RNN: B=8192, T=2048, I=2, H=20.
//  h_{t+1} = tanh(x_t @ W_ih^T + b_ih + b_hh + h_t @ W_hh^T)
//  out = h_T @ fc_w^T + fc_b ; h_state = h_T
//
// R2: warp-local pairs. 3 batch-pairs per warp (10 threads each, lanes 30/31
// dummy). h exchanged via per-warp double-buffered SMEM with ONE __syncwarp
// per timestep — no CTA barrier, warps fully independent so the SMSP arbiter
// overlaps one warp's tanh/LDS latency with another warp's FFMA2 stream.
// 2 batches packed per thread via fma.rn.f32x2; weights pre-scaled by
// 2*log2(e) so tanh = 1 - 2*rcp(ex2(A)+1).

#define Bq 8192
#define Tq 2048
#define Hq 20
#define NPAIR (Bq / 2)                           // 4096
#define PPW 3                                    // pairs per warp
#define NWARPS ((NPAIR + PPW - 1) / PPW)         // 1366
#define WPC 4                                    // warps per CTA
#define TPB (WPC * 32)                           // 128
#define NCTA ((NWARPS + WPC - 1) / WPC)          // 342

typedef unsigned long long u64;

__device__ __forceinline__ u64 pack2(float lo, float hi) {
    u64 r;
    asm("mov.b64 %0, {%1, %2};" : "=l"(r) : "f"(lo), "f"(hi));
    return r;
}
__device__ __forceinline__ void unpack2(u64 v, float& lo, float& hi) {
    asm("mov.b64 {%0, %1}, %2;" : "=f"(lo), "=f"(hi) : "l"(v));
}
__device__ __forceinline__ u64 fma2(u64 a, u64 b, u64 c) {
    u64 d;
    asm("fma.rn.f32x2 %0, %1, %2, %3;" : "=l"(d) : "l"(a), "l"(b), "l"(c));
    return d;
}
// Input A is already 2*log2(e)*a ; tanh(a) = 1 - 2/(2^A + 1)
__device__ __forceinline__ float tanh_scaled(float A) {
    float e;
    asm("ex2.approx.f32 %0, %1;" : "=f"(e) : "f"(A));
    float r;
    asm("rcp.approx.f32 %0, %1;" : "=f"(r) : "f"(e + 1.0f));
    return fmaf(-2.0f, r, 1.0f);
}

__global__ void __launch_bounds__(TPB)
rnn_kernel(const float* __restrict__ x,
           const float* __restrict__ Wih,
           const float* __restrict__ Whh,
           const float* __restrict__ bih,
           const float* __restrict__ bhh,
           const float* __restrict__ fcw,
           const float* __restrict__ fcb,
           float* __restrict__ out,   // [B]
           float* __restrict__ hs)    // [B, H]
{
    const float SC = 2.8853900817779268f;  // 2 * log2(e)

    const int lane  = threadIdx.x & 31;
    const int warp  = threadIdx.x >> 5;
    const int gwarp = blockIdx.x * WPC + warp;
    const int slot  = lane / 10;           // 0..2 real, 3 = dummy (lanes 30,31)
    const int sub   = lane % 10;
    const int pair  = gwarp * PPW + slot;
    const bool active = (slot < PPW) && (pair < NPAIR);
    const int pc  = active ? pair : 0;     // clamped for safe loads
    const int b0  = 2 * pc;
    const int b1  = 2 * pc + 1;
    const int j0  = 2 * sub;               // this thread's hidden rows
    const int j1  = j0 + 1;

    // ---- Per-thread constants (scaled by SC, splatted to f32x2) ----
    u64 wA[Hq], wB[Hq];
#pragma unroll
    for (int k = 0; k < Hq; k++) {
        float a = Whh[j0 * Hq + k] * SC;
        float b = Whh[j1 * Hq + k] * SC;
        wA[k] = pack2(a, a);
        wB[k] = pack2(b, b);
    }
    float wi00 = Wih[j0 * 2 + 0] * SC, wi01 = Wih[j0 * 2 + 1] * SC;
    float wi10 = Wih[j1 * 2 + 0] * SC, wi11 = Wih[j1 * 2 + 1] * SC;
    u64 wv00 = pack2(wi00, wi00), wv01 = pack2(wi01, wi01);
    u64 wv10 = pack2(wi10, wi10), wv11 = pack2(wi11, wi11);
    float bs0 = (bih[j0] + bhh[j0]) * SC;
    float bs1 = (bih[j1] + bhh[j1]) * SC;
    u64 bv0 = pack2(bs0, bs0), bv1 = pack2(bs1, bs1);

    // ---- Per-warp double-buffered hidden state (4 slots: 3 real + 1 dummy)
    // Slot stride 160B -> 8 banks apart; conflict-free, broadcast within slot.
    __shared__ u64 hsm[WPC][2][4][Hq];
    for (int i = threadIdx.x; i < WPC * 2 * 4 * Hq; i += TPB)
        (&hsm[0][0][0][0])[i] = 0ull;
    __syncthreads();   // one-time init only

    const float2* xp0 = (const float2*)(x + (size_t)b0 * Tq * 2);
    const float2* xp1 = (const float2*)(x + (size_t)b1 * Tq * 2);

    u64* buf0 = &hsm[warp][0][slot][0];
    u64* buf1 = &hsm[warp][1][slot][0];

    u64 r0 = 0, r1 = 0;  // this thread's latest h rows (packed)

    auto step = [&](const u64* __restrict__ rd, u64* __restrict__ wr,
                    float2 xa, float2 xb) {
        u64 xv0 = pack2(xa.x, xb.x);
        u64 xv1 = pack2(xa.y, xb.y);
        u64 acc0 = fma2(xv1, wv01, bv0); acc0 = fma2(xv0, wv00, acc0);
        u64 acc1 = fma2(xv1, wv11, bv1); acc1 = fma2(xv0, wv10, acc1);
        u64 hv[Hq];
#pragma unroll
        for (int k = 0; k < Hq; k++) hv[k] = rd[k];
#pragma unroll
        for (int k = 0; k < Hq; k++) {
            acc0 = fma2(hv[k], wA[k], acc0);
            acc1 = fma2(hv[k], wB[k], acc1);
        }
        float a0, a1, c0, c1;
        unpack2(acc0, a0, a1);
        unpack2(acc1, c0, c1);
        r0 = pack2(tanh_scaled(a0), tanh_scaled(a1));
        r1 = pack2(tanh_scaled(c0), tanh_scaled(c1));
        wr[j0] = r0;
        wr[j1] = r1;
        __syncwarp();   // warp-local: makes wr visible for next step's rd
    };

    // Software pipeline: x kept 2 steps ahead in registers.
    float2 xa0 = xp0[0], xb0 = xp1[0];   // t even
    float2 xa1 = xp0[1], xb1 = xp1[1];   // t odd

    for (int t = 0; t < Tq; t += 2) {
        int tn = (t + 2 < Tq) ? t + 2 : Tq - 1;
        float2 na = xp0[tn], nb = xp1[tn];
        step(buf0, buf1, xa0, xb0);      // t even : read buf0, write buf1
        xa0 = na; xb0 = nb;

        int tn2 = (t + 3 < Tq) ? t + 3 : Tq - 1;
        float2 na2 = xp0[tn2], nb2 = xp1[tn2];
        step(buf1, buf0, xa1, xb1);      // t odd  : read buf1, write buf0
        xa1 = na2; xb1 = nb2;
    }
    // T=2048 even -> final h_T resides in buf0; r0/r1 hold this thread's rows.

    if (active) {
        float v0, v1;
        unpack2(r0, v0, v1);
        hs[(size_t)b0 * Hq + j0] = v0;
        hs[(size_t)b1 * Hq + j0] = v1;
        unpack2(r1, v0, v1);
        hs[(size_t)b0 * Hq + j1] = v0;
        hs[(size_t)b1 * Hq + j1] = v1;

        if (sub == 0) {
            // slot-mates' last writes happened before the final __syncwarp we
            // already passed; no further writes occur -> safe to read buf0.
            float s0 = fcb[0], s1 = fcb[0];
#pragma unroll
            for (int k = 0; k < Hq; k++) {
                float lo, hi;
                unpack2(buf0[k], lo, hi);
                float w = fcw[k];
                s0 = fmaf(w, lo, s0);
                s1 = fmaf(w, hi, s1);
            }
            out[b0] = s0;
            out[b1] = s1;
        }
    }
}

extern "C" void kernel_launch(void* const* d_in, const int* in_sizes, int n_in,
                              void* d_out, int out_size) {
    const float* x   = (const float*)d_in[0];
    const float* Wih = (const float*)d_in[1];
    const float* Whh = (const float*)d_in[2];
    const float* bih = (const float*)d_in[3];
    const float* bhh = (const float*)d_in[4];
    const float* fcw = (const float*)d_in[5];
    const float* fcb = (const float*)d_in[6];
    float* out = (float*)d_out;            // first B floats: fc output
    float* hs  = out + Bq;                 // next B*H floats: h_state
    rnn_kernel<<<NCTA, TPB>>>(x, Wih, Whh, bih, bhh, fcw, fcb, out, hs);
}

// round 3
// speedup vs baseline: 1.9542x; 1.1396x over previous
#include <cuda_runtime.h>

// RNN: B=8192, T=2048, I=2, H=20.
//  h_{t+1} = tanh(x_t @ W_ih^T + b_ih + b_hh + h_t @ W_hh^T)
//  out = h_T @ fc_w^T + fc_b ; h_state = h_T
//
// R3: registers unlocked (launch_bounds 320,1 -> 204 regs; the 40 packed
// W_hh rows = 160 regs now stay resident). Uniform grid 148x10 warps
// (1 CTA/SM). h exchange via LDS.128/STS.128 (conflict-free slot layout).
// x folded into per-step bias 'binit' one 4-step block ahead of use
// (covers DRAM latency). One __syncwarp per step; warps independent.

#define Bq 8192
#define Tq 2048
#define Hq 20
#define NPAIR (Bq / 2)      // 4096
#define PPW 3               // pairs (slots) per warp, lanes 0..29
#define WPC 10              // warps per CTA
#define TPB (WPC * 32)      // 320
#define NCTA 148            // exactly 1 CTA per SM; 1480 warps >= 1366 needed

typedef unsigned long long u64;

__device__ __forceinline__ u64 pack2(float lo, float hi) {
    u64 r;
    asm("mov.b64 %0, {%1, %2};" : "=l"(r) : "f"(lo), "f"(hi));
    return r;
}
__device__ __forceinline__ void unpack2(u64 v, float& lo, float& hi) {
    asm("mov.b64 {%0, %1}, %2;" : "=f"(lo), "=f"(hi) : "l"(v));
}
__device__ __forceinline__ u64 fma2(u64 a, u64 b, u64 c) {
    u64 d;
    asm("fma.rn.f32x2 %0, %1, %2, %3;" : "=l"(d) : "l"(a), "l"(b), "l"(c));
    return d;
}
// Input A is already 2*log2(e)*a ; tanh(a) = 1 - 2/(2^A + 1)
__device__ __forceinline__ float tanh_scaled(float A) {
    float e;
    asm("ex2.approx.f32 %0, %1;" : "=f"(e) : "f"(A));
    float r;
    asm("rcp.approx.f32 %0, %1;" : "=f"(r) : "f"(e + 1.0f));
    return fmaf(-2.0f, r, 1.0f);
}

__global__ void __launch_bounds__(TPB, 1)
rnn_kernel(const float* __restrict__ x,
           const float* __restrict__ Wih,
           const float* __restrict__ Whh,
           const float* __restrict__ bih,
           const float* __restrict__ bhh,
           const float* __restrict__ fcw,
           const float* __restrict__ fcb,
           float* __restrict__ out,   // [B]
           float* __restrict__ hs)    // [B, H]
{
    const float SC = 2.8853900817779268f;  // 2 * log2(e)

    const int lane  = threadIdx.x & 31;
    const int warp  = threadIdx.x >> 5;
    const int gwarp = blockIdx.x * WPC + warp;
    const int slot  = lane / 10;           // 0..2 real, 3 = dummy (lanes 30,31)
    const int sub   = lane % 10;
    const int pair  = gwarp * PPW + slot;
    const bool active = (slot < PPW) && (pair < NPAIR);
    const int pc  = active ? pair : 0;     // clamped for safe loads
    const int b0  = 2 * pc;
    const int b1  = 2 * pc + 1;
    const int j0  = 2 * sub;               // this thread's hidden rows
    const int j1  = j0 + 1;

    // ---- Per-thread constants (scaled by SC, splatted to f32x2) ----
    u64 wA[Hq], wB[Hq];                    // 40 u64 = 160 regs (resident!)
#pragma unroll
    for (int k = 0; k < Hq; k++) {
        float a = Whh[j0 * Hq + k] * SC;
        float b = Whh[j1 * Hq + k] * SC;
        wA[k] = pack2(a, a);
        wB[k] = pack2(b, b);
    }
    float wi00 = Wih[j0 * 2 + 0] * SC, wi01 = Wih[j0 * 2 + 1] * SC;
    float wi10 = Wih[j1 * 2 + 0] * SC, wi11 = Wih[j1 * 2 + 1] * SC;
    u64 wv00 = pack2(wi00, wi00), wv01 = pack2(wi01, wi01);
    u64 wv10 = pack2(wi10, wi10), wv11 = pack2(wi11, wi11);
    float bs0 = (bih[j0] + bhh[j0]) * SC;
    float bs1 = (bih[j1] + bhh[j1]) * SC;
    u64 bv0 = pack2(bs0, bs0), bv1 = pack2(bs1, bs1);

    // ---- Per-warp double-buffered hidden state (4 slots: 3 real + 1 dummy)
    // Slot stride 160B -> starting banks 0/8/16/24; LDS.128 conflict-free.
    __shared__ __align__(16) u64 hsm[WPC][2][4][Hq];
    for (int i = threadIdx.x; i < WPC * 2 * 4 * Hq; i += TPB)
        (&hsm[0][0][0][0])[i] = 0ull;
    __syncthreads();   // one-time init only

    const float2* xp0 = (const float2*)(x + (size_t)b0 * Tq * 2);
    const float2* xp1 = (const float2*)(x + (size_t)b1 * Tq * 2);

    u64* buf0 = &hsm[warp][0][slot][0];
    u64* buf1 = &hsm[warp][1][slot][0];

    u64 r0 = 0, r1 = 0;  // this thread's latest h rows (packed)

    // step t: read rd (= h_t), write wr (= h_{t+1}); bi = b + x_t @ W_ih^T
    auto step = [&](const u64* __restrict__ rd, u64* __restrict__ wr,
                    u64 bi0, u64 bi1) {
        u64 acc0 = bi0, acc1 = bi1;
#pragma unroll
        for (int m = 0; m < Hq / 2; m++) {
            ulonglong2 hv = *(const ulonglong2*)(rd + 2 * m);   // LDS.128
            acc0 = fma2(hv.x, wA[2 * m], acc0);
            acc1 = fma2(hv.x, wB[2 * m], acc1);
            acc0 = fma2(hv.y, wA[2 * m + 1], acc0);
            acc1 = fma2(hv.y, wB[2 * m + 1], acc1);
        }
        float a0, a1, c0, c1;
        unpack2(acc0, a0, a1);
        unpack2(acc1, c0, c1);
        r0 = pack2(tanh_scaled(a0), tanh_scaled(a1));
        r1 = pack2(tanh_scaled(c0), tanh_scaled(c1));
        *(ulonglong2*)(wr + j0) = make_ulonglong2(r0, r1);      // STS.128
        __syncwarp();
    };

    auto binit0 = [&](float2 xa, float2 xb) {
        return fma2(pack2(xa.x, xb.x), wv00,
               fma2(pack2(xa.y, xb.y), wv01, bv0));
    };
    auto binit1 = [&](float2 xa, float2 xb) {
        return fma2(pack2(xa.x, xb.x), wv10,
               fma2(pack2(xa.y, xb.y), wv11, bv1));
    };

    // ---- x pipeline: bq holds binit for the current 4-step block;
    //      xr holds raw x for the NEXT block (one full block of LDG cover).
    float2 xr0[4], xr1[4];
    u64 bq0[4], bq1[4];
#pragma unroll
    for (int i = 0; i < 4; i++) { xr0[i] = xp0[i]; xr1[i] = xp1[i]; }
#pragma unroll
    for (int i = 0; i < 4; i++) {
        bq0[i] = binit0(xr0[i], xr1[i]);
        bq1[i] = binit1(xr0[i], xr1[i]);
    }
#pragma unroll
    for (int i = 0; i < 4; i++) { xr0[i] = xp0[4 + i]; xr1[i] = xp1[4 + i]; }

#pragma unroll 1
    for (int tb = 0; tb < Tq; tb += 4) {
        step(buf0, buf1, bq0[0], bq1[0]);   // t even : read buf0, write buf1
        step(buf1, buf0, bq0[1], bq1[1]);
        step(buf0, buf1, bq0[2], bq1[2]);
        step(buf1, buf0, bq0[3], bq1[3]);
        // fold x (loaded a full block ago) into next block's binit
#pragma unroll
        for (int i = 0; i < 4; i++) {
            bq0[i] = binit0(xr0[i], xr1[i]);
            bq1[i] = binit1(xr0[i], xr1[i]);
        }
        // prefetch x for block tb+8 (clamped; tail loads unused)
#pragma unroll
        for (int i = 0; i < 4; i++) {
            int tt = tb + 8 + i;
            if (tt >= Tq) tt = Tq - 1;
            xr0[i] = xp0[tt];
            xr1[i] = xp1[tt];
        }
    }
    // T=2048 even -> final h_T resides in buf0; r0/r1 hold this thread's rows.

    if (active) {
        float v0, v1;
        unpack2(r0, v0, v1);
        hs[(size_t)b0 * Hq + j0] = v0;
        hs[(size_t)b1 * Hq + j0] = v1;
        unpack2(r1, v0, v1);
        hs[(size_t)b0 * Hq + j1] = v0;
        hs[(size_t)b1 * Hq + j1] = v1;

        if (sub == 0) {
            // all slot-mates' final writes precede the last __syncwarp.
            float s0 = fcb[0], s1 = fcb[0];
#pragma unroll
            for (int k = 0; k < Hq; k++) {
                float lo, hi;
                unpack2(buf0[k], lo, hi);
                float w = fcw[k];
                s0 = fmaf(w, lo, s0);
                s1 = fmaf(w, hi, s1);
            }
            out[b0] = s0;
            out[b1] = s1;
        }
    }
}

extern "C" void kernel_launch(void* const* d_in, const int* in_sizes, int n_in,
                              void* d_out, int out_size) {
    const float* x   = (const float*)d_in[0];
    const float* Wih = (const float*)d_in[1];
    const float* Whh = (const float*)d_in[2];
    const float* bih = (const float*)d_in[3];
    const float* bhh = (const float*)d_in[4];
    const float* fcw = (const float*)d_in[5];
    const float* fcb = (const float*)d_in[6];
    float* out = (float*)d_out;            // first B floats: fc output
    float* hs  = out + Bq;                 // next B*H floats: h_state
    rnn_kernel<<<NCTA, TPB>>>(x, Wih, Whh, bih, bhh, fcw, fcb, out, hs);
}